// round 16
// baseline (speedup 1.0000x reference)
#include <cuda_runtime.h>
#include <cuda_fp16.h>
#include <cstdint>

// Problem constants
#define NB     4
#define LSEQ   4096
#define ROWS   16384
#define DIMV   512
#define HID2   2048
#define HIDV   1024
#define QKD    128
#define OUTD   8

#define A_SCALE 1099511627776.0f        // 2^40  (exact)
#define A_INV   9.094947017729282e-13f  // 2^-40 (exact)

// ------------------------- scratch (static device globals) -------------------
__device__ __half g_normed[(size_t)ROWS * DIMV];     // quad16 layout
__device__ __half g_Wh16 [(size_t)DIMV * HID2];      // plain [k][n]
__device__ __half g_Wqk16[(size_t)DIMV * QKD];       // plain [k][n]
__device__ __half g_v16  [(size_t)ROWS * HIDV];      // plain [token][n]
__device__ float  g_gate [(size_t)ROWS * HIDV];      // fp32
__device__ __half g_q16  [(size_t)ROWS * QKD];       // quad16 layout
__device__ __half g_k16  [(size_t)ROWS * QKD];       // plain [token][128]
__device__ __half g_A16  [(size_t)NB * LSEQ * LSEQ]; // quad16 per batch (xA_SCALE)
__device__ float  g_V    [(size_t)ROWS * HIDV];      // fp32

// ------------------------------ helpers --------------------------------------
__device__ __forceinline__ uint32_t smem_u32(const void* p) {
    uint32_t a;
    asm("{ .reg .u64 t; cvta.to.shared.u64 t, %1; cvt.u32.u64 %0, t; }" : "=r"(a) : "l"(p));
    return a;
}
__device__ __forceinline__ void cp16(uint32_t s, const void* g) {
    asm volatile("cp.async.cg.shared.global [%0], [%1], 16;" :: "r"(s), "l"(g));
}
#define CP_COMMIT() asm volatile("cp.async.commit_group;" ::: "memory")
#define CP_WAIT0()  asm volatile("cp.async.wait_group 0;" ::: "memory")
#define CP_WAIT1()  asm volatile("cp.async.wait_group 1;" ::: "memory")

__device__ __forceinline__ void mma_f16(float* c, const uint32_t* a, const uint32_t* b) {
    asm volatile(
        "mma.sync.aligned.m16n8k16.row.col.f32.f16.f16.f32 "
        "{%0,%1,%2,%3},{%4,%5,%6,%7},{%8,%9},{%0,%1,%2,%3};"
        : "+f"(c[0]), "+f"(c[1]), "+f"(c[2]), "+f"(c[3])
        : "r"(a[0]), "r"(a[1]), "r"(a[2]), "r"(a[3]), "r"(b[0]), "r"(b[1]));
}
// fp16-accumulate MMA with C = 0: D(4 halves) = A*B over K=16 only.
__device__ __forceinline__ void mma_f16h0(uint32_t& d0, uint32_t& d1,
                                          const uint32_t* a, const uint32_t* b) {
    asm volatile(
        "mma.sync.aligned.m16n8k16.row.col.f16.f16.f16.f16 "
        "{%0,%1},{%2,%3,%4,%5},{%6,%7},{%8,%9};"
        : "=r"(d0), "=r"(d1)
        : "r"(a[0]), "r"(a[1]), "r"(a[2]), "r"(a[3]), "r"(b[0]), "r"(b[1]),
          "r"(0u), "r"(0u));
}
__device__ __forceinline__ void ldsm_x4_t(uint32_t* r, uint32_t addr) {
    asm volatile("ldmatrix.sync.aligned.m8n8.x4.trans.shared.b16 {%0,%1,%2,%3}, [%4];"
        : "=r"(r[0]), "=r"(r[1]), "=r"(r[2]), "=r"(r[3]) : "r"(addr));
}
__device__ __forceinline__ void ldsm_x4(uint32_t* r, uint32_t addr) {
    asm volatile("ldmatrix.sync.aligned.m8n8.x4.shared.b16 {%0,%1,%2,%3}, [%4];"
        : "=r"(r[0]), "=r"(r[1]), "=r"(r[2]), "=r"(r[3]) : "r"(addr));
}

// quad16 A-layout: 16m x 16k blocks of 256 halves; a thread's m16n8k16 A
// fragment (8 halves) is contiguous (1 LDS.128).
__device__ __forceinline__ size_t q16_off(int m, int k, int K16) {
    return ((size_t)(m >> 4) * K16 + (k >> 4)) * 256
         + (size_t)((((m & 7) << 2) + ((k & 7) >> 1)) * 8
                    + ((k >> 3) & 1) * 4 + ((m >> 3) & 1) * 2 + (k & 1));
}
__device__ __forceinline__ uint32_t packh2(float a, float b) {
    __half2 h = __floats2half2_rn(a, b);
    return *(uint32_t*)&h;
}

// ------------------------------ LayerNorm (quad16 fp16 out) ------------------
__global__ void ln_kernel(const float* __restrict__ x, const float* __restrict__ g,
                          const float* __restrict__ b, __half* __restrict__ o) {
    int row = blockIdx.x;
    int t = threadIdx.x;
    const float4* xr = (const float4*)(x + (size_t)row * DIMV);
    float4 xv = xr[t];
    float s  = xv.x + xv.y + xv.z + xv.w;
    float ss = xv.x*xv.x + xv.y*xv.y + xv.z*xv.z + xv.w*xv.w;
    #pragma unroll
    for (int off = 16; off; off >>= 1) {
        s  += __shfl_xor_sync(0xffffffffu, s,  off);
        ss += __shfl_xor_sync(0xffffffffu, ss, off);
    }
    __shared__ float sh_s[4], sh_ss[4];
    if ((t & 31) == 0) { sh_s[t >> 5] = s; sh_ss[t >> 5] = ss; }
    __syncthreads();
    s  = sh_s[0] + sh_s[1] + sh_s[2] + sh_s[3];
    ss = sh_ss[0] + sh_ss[1] + sh_ss[2] + sh_ss[3];
    float mu  = s * (1.0f / DIMV);
    float var = ss * (1.0f / DIMV) - mu * mu;
    float inv = rsqrtf(var + 1e-5f);
    float4 gv = ((const float4*)g)[t];
    float4 bv = ((const float4*)b)[t];
    float r0 = (xv.x - mu) * inv * gv.x + bv.x;
    float r1 = (xv.y - mu) * inv * gv.y + bv.y;
    float r2 = (xv.z - mu) * inv * gv.z + bv.z;
    float r3 = (xv.w - mu) * inv * gv.w + bv.w;
    int d0 = t * 4;
    *(uint32_t*)(o + q16_off(row, d0,     DIMV / 16)) = packh2(r0, r1);
    *(uint32_t*)(o + q16_off(row, d0 + 2, DIMV / 16)) = packh2(r2, r3);
}

// --------------------------- fp16 rounding copy (plain) ----------------------
__global__ void round16(const float* __restrict__ s, __half* __restrict__ d, int n) {
    int i = blockIdx.x * blockDim.x + threadIdx.x;
    if (i < n) d[i] = __float2half_rn(s[i]);
}

// --------------------------- fp16 tensor-core GEMM ---------------------------
// D[m][n] = sum_k A[m][k]*B[k][n];  A quad16 (LDS.128 frags).
// Accumulation: EPI!=2 -> fp32-acc HMMA (rt~16).
//               EPI==2 (AV) -> fp16-acc HMMA with C=0 (rt~8), K=16 chunk
//                              promoted immediately into fp32 accs.
// B smem: plain rows, pitch 136 halves (conflict-free ldmatrix).
// BL=0: B global [k][n]      -> ldmatrix.x4.trans  (rows = k)
// BL=1: B global [token][k]  -> ldmatrix.x4        (rows = token n)
// CTA 128x128, 8 warps, warp tile 64x32. NST=3: one-barrier pipeline; NST=1 single.
// EPI 0 (Wh): s=silu(acc+a0[n]); n<HIDV -> v16 plain; else gate fp32
// EPI 1 (qkT): A16 quad16 = fp16(relu(acc*scale)^2 * A_SCALE)
// EPI 2 (AV): V = acc * A_INV * gate[(z*4096+m)*HIDV+n]
// EPI 3 (Z):  s=silu(acc+a0[n]); q16 quad16; k16 plain
template<int EPI, int BL, int BK, int NST>
__global__ void __launch_bounds__(256, 2)
tgemm(const __half* __restrict__ Ag, int K16g, size_t sA,
      const __half* __restrict__ Bh, int ldbh, size_t sBh,
      void* __restrict__ C0, void* __restrict__ C1,
      int K,
      const float* __restrict__ a0, const float* __restrict__ a1,
      const float* __restrict__ a2, size_t sAux, float scale)
{
    constexpr int KB16   = BK / 16;
    constexpr int ASTG_H = 128 * BK;                       // halves per A stage
    constexpr int BROWS  = BL ? 128 : BK;
    constexpr int BSTG_H = BROWS * 136;

    extern __shared__ __half smh[];
    __half* Asm = smh;
    __half* Bsm = smh + NST * ASTG_H;
    const uint32_t sbA = smem_u32(Asm);
    const uint32_t sbB = smem_u32(Bsm);
    (void)sbA;

    const int z = blockIdx.z;
    const __half* A = Ag + z * sA;
    const __half* B = Bh + z * sBh;
    const float* ax = a0 + z * sAux;

    const int tid  = threadIdx.x;
    const int warp = tid >> 5;
    const int lane = tid & 31;
    const int grp  = lane >> 2;
    const int tig  = lane & 3;
    const int mw   = (warp >> 2) * 64;
    const int nw   = (warp & 3) * 32;
    const int m0 = blockIdx.y * 128, n0 = blockIdx.x * 128;
    const int mbb = (mw >> 4);

    // per-lane ldmatrix base offset (halves, within a stage)
    const int bOff = BL
        ? ((nw + (lane & 7) + 8 * (lane >> 4)) * 136 + 8 * ((lane >> 3) & 1))
        : ((lane & 15) * 136 + (lane >> 4) * 8 + nw);

    float acc[4][4][4];
    #pragma unroll
    for (int mi = 0; mi < 4; mi++)
        #pragma unroll
        for (int ni = 0; ni < 4; ni++)
            #pragma unroll
            for (int r = 0; r < 4; r++) acc[mi][ni][r] = 0.0f;

    auto load_stage = [&](int st, int k0) {
        // A: quad16 blocks, 16B chunks
        #pragma unroll
        for (int l = 0; l < BK / 16; l++) {
            int qc = tid + l * 256;
            int blk = qc >> 5, c = qc & 31;
            int mbl = blk / KB16, kbl = blk - mbl * KB16;
            const __half* gsrc = A + ((size_t)(m0 / 16 + mbl) * K16g + (k0 / 16 + kbl)) * 256 + c * 8;
            cp16(sbB - (NST * ASTG_H - (uint32_t)(st * ASTG_H + blk * 256 + c * 8)) * 2 - 0 + 0
                 , gsrc);
        }
        // B: BROWS rows x 128 halves, 16 chunks/row
        if (BL == 0) {
            #pragma unroll
            for (int l = 0; l < BK / 16; l++) {
                int id = tid + l * 256;
                int r = id >> 4, c = id & 15;
                cp16(sbB + (uint32_t)(st * BSTG_H + r * 136 + c * 8) * 2,
                     B + (size_t)(k0 + r) * ldbh + n0 + c * 8);
            }
        } else {
            #pragma unroll
            for (int l = 0; l < 8; l++) {
                int id = tid + l * 256;
                int r = id >> 4, c = id & 15;
                cp16(sbB + (uint32_t)(st * BSTG_H + r * 136 + c * 8) * 2,
                     B + (size_t)(n0 + r) * ldbh + k0 + c * 8);
            }
        }
        CP_COMMIT();
    };

    auto compute_stage = [&](int st) {
        const __half* As = Asm + st * ASTG_H;
        const uint32_t sbBs = sbB + (uint32_t)(st * BSTG_H) * 2;
        #pragma unroll
        for (int s = 0; s < KB16; s++) {
            uint32_t afr[4][4], bq0[4], bq1[4];
            #pragma unroll
            for (int mi = 0; mi < 4; mi++) {
                uint4 av = *(const uint4*)(As + (((mbb + mi) * KB16 + s) * 256 + lane * 8));
                afr[mi][0] = av.x; afr[mi][1] = av.y; afr[mi][2] = av.z; afr[mi][3] = av.w;
            }
            if (BL == 0) {
                ldsm_x4_t(bq0, sbBs + (uint32_t)(s * 2176 + bOff) * 2);
                ldsm_x4_t(bq1, sbBs + (uint32_t)(s * 2176 + bOff + 16) * 2);
            } else {
                ldsm_x4(bq0, sbBs + (uint32_t)(s * 16 + bOff) * 2);
                ldsm_x4(bq1, sbBs + (uint32_t)(s * 16 + bOff + 16 * 136) * 2);
            }
            uint32_t bfr[4][2] = {
                { bq0[0], bq0[1] }, { bq0[2], bq0[3] },
                { bq1[0], bq1[1] }, { bq1[2], bq1[3] } };
            #pragma unroll
            for (int mi = 0; mi < 4; mi++)
                #pragma unroll
                for (int ni = 0; ni < 4; ni++) {
                    if (EPI == 2) {
                        uint32_t d0, d1;
                        mma_f16h0(d0, d1, afr[mi], bfr[ni]);
                        float2 f0 = __half22float2(*(__half2*)&d0);
                        float2 f1 = __half22float2(*(__half2*)&d1);
                        acc[mi][ni][0] += f0.x; acc[mi][ni][1] += f0.y;
                        acc[mi][ni][2] += f1.x; acc[mi][ni][3] += f1.y;
                    } else {
                        mma_f16(acc[mi][ni], afr[mi], bfr[ni]);
                    }
                }
        }
    };

    const int niter = K / BK;
    if (NST == 1) {
        load_stage(0, 0);
        CP_WAIT0();
        __syncthreads();
        compute_stage(0);
    } else {
        load_stage(0, 0);
        if (niter > 1) load_stage(1, BK);
        for (int it = 0; it < niter; it++) {
            if (it + 1 < niter) { CP_WAIT1(); }
            else                { CP_WAIT0(); }
            __syncthreads();
            if (it + 2 < niter) load_stage((it + 2) % NST, (it + 2) * BK);
            compute_stage(it % NST);
        }
    }
    __syncthreads();

    // ------------------------------ epilogue ---------------------------------
    #pragma unroll
    for (int mi = 0; mi < 4; mi++) {
        #pragma unroll
        for (int half = 0; half < 2; half++) {
            int m = m0 + mw + mi * 16 + grp + half * 8;
            #pragma unroll
            for (int ni = 0; ni < 4; ni++) {
                int n = n0 + nw + ni * 8 + tig * 2;
                float v0 = acc[mi][ni][half * 2 + 0];
                float v1 = acc[mi][ni][half * 2 + 1];
                if (EPI == 0) {
                    v0 += a0[n];     v1 += a0[n + 1];
                    v0 = v0 / (1.0f + __expf(-v0));
                    v1 = v1 / (1.0f + __expf(-v1));
                    if (n < HIDV) {
                        __half* vv = (__half*)C0;
                        *(uint32_t*)(vv + (size_t)m * HIDV + n) = packh2(v0, v1);
                    } else {
                        float* gb = (float*)C1;
                        *(float2*)(gb + (size_t)m * HIDV + (n - HIDV)) = make_float2(v0, v1);
                    }
                } else if (EPI == 1) {
                    float t0 = fmaxf(v0 * scale, 0.0f);
                    float t1 = fmaxf(v1 * scale, 0.0f);
                    __half* Az = (__half*)C0 + (size_t)z * LSEQ * LSEQ;
                    *(uint32_t*)(Az + q16_off(m, n, LSEQ / 16)) =
                        packh2(t0 * t0 * A_SCALE, t1 * t1 * A_SCALE);
                } else if (EPI == 2) {
                    float* Vp = (float*)C0 + (size_t)z * LSEQ * HIDV;
                    v0 *= A_INV * ax[(size_t)m * HIDV + n];
                    v1 *= A_INV * ax[(size_t)m * HIDV + n + 1];
                    *(float2*)(Vp + (size_t)m * HIDV + n) = make_float2(v0, v1);
                } else {   // EPI 3
                    v0 += a0[n];     v1 += a0[n + 1];
                    v0 = v0 / (1.0f + __expf(-v0));
                    v1 = v1 / (1.0f + __expf(-v1));
                    __half* qb = (__half*)C0;
                    __half* kb = (__half*)C1;
                    *(uint32_t*)(qb + q16_off(m, n, QKD / 16)) =
                        packh2(v0 * a1[n] + a2[n], v1 * a1[n + 1] + a2[n + 1]);
                    *(uint32_t*)(kb + (size_t)m * QKD + n) =
                        packh2(v0 * a1[QKD + n] + a2[QKD + n],
                               v1 * a1[QKD + n + 1] + a2[QKD + n + 1]);
                }
            }
        }
    }
}

// ------------------------- output projection (1024 -> 8) ---------------------
__global__ void out_kernel(const float* __restrict__ Vg, const float* __restrict__ Wo,
                           const float* __restrict__ bo, float* __restrict__ out) {
    int row  = blockIdx.x * (blockDim.x >> 5) + (threadIdx.x >> 5);
    int lane = threadIdx.x & 31;
    const float* vr = Vg + (size_t)row * HIDV;
    float acc[OUTD];
    #pragma unroll
    for (int o = 0; o < OUTD; o++) acc[o] = 0.0f;
    for (int kk = lane; kk < HIDV; kk += 32) {
        float v = vr[kk];
        const float* w = Wo + (size_t)kk * OUTD;
        #pragma unroll
        for (int o = 0; o < OUTD; o++) acc[o] += v * w[o];
    }
    #pragma unroll
    for (int o = 0; o < OUTD; o++) {
        #pragma unroll
        for (int off = 16; off; off >>= 1)
            acc[o] += __shfl_xor_sync(0xffffffffu, acc[o], off);
    }
    if (lane < OUTD) out[(size_t)row * OUTD + lane] = acc[lane] + bo[lane];
}

// --------------------------------- launch ------------------------------------
extern "C" void kernel_launch(void* const* d_in, const int* in_sizes, int n_in,
                              void* d_out, int out_size) {
    const float* x     = (const float*)d_in[0];
    const float* ln_g  = (const float*)d_in[1];
    const float* ln_b  = (const float*)d_in[2];
    const float* Wh    = (const float*)d_in[3];
    const float* bh    = (const float*)d_in[4];
    const float* Wqk   = (const float*)d_in[5];
    const float* bqk   = (const float*)d_in[6];
    const float* gamma = (const float*)d_in[7];
    const float* beta  = (const float*)d_in[8];
    const float* Wo    = (const float*)d_in[9];
    const float* bo    = (const float*)d_in[10];
    float* out = (float*)d_out;

    __half *normed, *Wh16, *Wqk16, *v16, *q16, *k16, *A16;
    float *gate, *V;
    cudaGetSymbolAddress((void**)&normed, g_normed);
    cudaGetSymbolAddress((void**)&Wh16,   g_Wh16);
    cudaGetSymbolAddress((void**)&Wqk16,  g_Wqk16);
    cudaGetSymbolAddress((void**)&v16,    g_v16);
    cudaGetSymbolAddress((void**)&gate,   g_gate);
    cudaGetSymbolAddress((void**)&q16,    g_q16);
    cudaGetSymbolAddress((void**)&k16,    g_k16);
    cudaGetSymbolAddress((void**)&A16,    g_A16);
    cudaGetSymbolAddress((void**)&V,      g_V);

    // smem: BK64/NST3: (3*8192 + 3*8704)*2 = 101376 B
    //       BK128/NST1: (16384 + 17408)*2  = 67584 B
    const int SM_P = 101376, SM_Q = 67584;
    static bool attr_done = false;
    if (!attr_done) {
        cudaFuncSetAttribute(tgemm<0,0,64,3>,  cudaFuncAttributeMaxDynamicSharedMemorySize, SM_P);
        cudaFuncSetAttribute(tgemm<3,0,64,3>,  cudaFuncAttributeMaxDynamicSharedMemorySize, SM_P);
        cudaFuncSetAttribute(tgemm<1,1,128,1>, cudaFuncAttributeMaxDynamicSharedMemorySize, SM_Q);
        cudaFuncSetAttribute(tgemm<2,0,64,3>,  cudaFuncAttributeMaxDynamicSharedMemorySize, SM_P);
        attr_done = true;
    }

    // 0. weights -> fp16 (plain row-major)
    round16<<<(DIMV * HID2 + 255) / 256, 256>>>(Wh,  Wh16,  DIMV * HID2);
    round16<<<(DIMV * QKD  + 255) / 256, 256>>>(Wqk, Wqk16, DIMV * QKD);

    // 1. LayerNorm -> normed (quad16 fp16)
    ln_kernel<<<ROWS, 128>>>(x, ln_g, ln_b, normed);

    // 2. Wh GEMM: hidden -> v16 (plain) + gate (fp32)
    tgemm<0,0,64,3><<<dim3(HID2 / 128, ROWS / 128, 1), 256, SM_P>>>(
        normed, DIMV / 16, 0, Wh16, HID2, 0,
        v16, gate, DIMV, bh, nullptr, nullptr, 0, 0.0f);

    // 3. Z GEMM fused silu + affine -> q16 (quad16), k16 (plain)
    tgemm<3,0,64,3><<<dim3(1, ROWS / 128, 1), 256, SM_P>>>(
        normed, DIMV / 16, 0, Wqk16, QKD, 0,
        q16, k16, DIMV, bqk, gamma, beta, 0, 0.0f);

    // 4. qkT per batch (K=128, single stage): A16 = fp16(relu(./L)^2 * 2^40)
    tgemm<1,1,128,1><<<dim3(LSEQ / 128, LSEQ / 128, NB), 256, SM_Q>>>(
        q16, QKD / 16, (size_t)LSEQ * QKD, k16, QKD, (size_t)LSEQ * QKD,
        A16, nullptr, QKD, nullptr, nullptr, nullptr, 0, 1.0f / LSEQ);

    // 5. AV per batch: V = (A@v) * 2^-40 * gate  (fp16-chunk accumulation)
    tgemm<2,0,64,3><<<dim3(HIDV / 128, LSEQ / 128, NB), 256, SM_P>>>(
        A16, LSEQ / 16, (size_t)LSEQ * LSEQ, v16, HIDV, (size_t)LSEQ * HIDV,
        V, nullptr, LSEQ, gate, nullptr, nullptr, (size_t)LSEQ * HIDV, 0.0f);

    // 6. out = V @ Wo + bo
    out_kernel<<<ROWS / 8, 256>>>(V, Wo, bo, out);
}

// round 17
// speedup vs baseline: 1.2744x; 1.2744x over previous
#include <cuda_runtime.h>
#include <cuda_fp16.h>
#include <cstdint>

// Problem constants
#define NB     4
#define LSEQ   4096
#define ROWS   16384
#define DIMV   512
#define HID2   2048
#define HIDV   1024
#define QKD    128
#define OUTD   8

#define A_SCALE 1099511627776.0f        // 2^40  (exact)
#define A_INV   9.094947017729282e-13f  // 2^-40 (exact)

// ------------------------- scratch (static device globals) -------------------
__device__ __half g_normed[(size_t)ROWS * DIMV];     // quad16 layout
__device__ __half g_Wh16 [(size_t)DIMV * HID2];      // plain [k][n]
__device__ __half g_Wqk16[(size_t)DIMV * QKD];       // plain [k][n]
__device__ __half g_v16  [(size_t)ROWS * HIDV];      // plain [token][n]
__device__ float  g_gate [(size_t)ROWS * HIDV];      // fp32
__device__ __half g_q16  [(size_t)ROWS * QKD];       // quad16 layout
__device__ __half g_k16  [(size_t)ROWS * QKD];       // plain [token][128]
__device__ __half g_A16  [(size_t)NB * LSEQ * LSEQ]; // quad16 per batch (xA_SCALE)
__device__ float  g_V    [(size_t)ROWS * HIDV];      // fp32

// ------------------------------ helpers --------------------------------------
__device__ __forceinline__ uint32_t smem_u32(const void* p) {
    uint32_t a;
    asm("{ .reg .u64 t; cvta.to.shared.u64 t, %1; cvt.u32.u64 %0, t; }" : "=r"(a) : "l"(p));
    return a;
}
__device__ __forceinline__ void cp16(uint32_t s, const void* g) {
    asm volatile("cp.async.cg.shared.global [%0], [%1], 16;" :: "r"(s), "l"(g));
}
#define CP_COMMIT() asm volatile("cp.async.commit_group;" ::: "memory")
#define CP_WAIT0()  asm volatile("cp.async.wait_group 0;" ::: "memory")
#define CP_WAIT1()  asm volatile("cp.async.wait_group 1;" ::: "memory")

__device__ __forceinline__ void mma_f16(float* c, const uint32_t* a, const uint32_t* b) {
    asm volatile(
        "mma.sync.aligned.m16n8k16.row.col.f32.f16.f16.f32 "
        "{%0,%1,%2,%3},{%4,%5,%6,%7},{%8,%9},{%0,%1,%2,%3};"
        : "+f"(c[0]), "+f"(c[1]), "+f"(c[2]), "+f"(c[3])
        : "r"(a[0]), "r"(a[1]), "r"(a[2]), "r"(a[3]), "r"(b[0]), "r"(b[1]));
}
__device__ __forceinline__ void ldsm_x4_t(uint32_t* r, uint32_t addr) {
    asm volatile("ldmatrix.sync.aligned.m8n8.x4.trans.shared.b16 {%0,%1,%2,%3}, [%4];"
        : "=r"(r[0]), "=r"(r[1]), "=r"(r[2]), "=r"(r[3]) : "r"(addr));
}
__device__ __forceinline__ void ldsm_x4(uint32_t* r, uint32_t addr) {
    asm volatile("ldmatrix.sync.aligned.m8n8.x4.shared.b16 {%0,%1,%2,%3}, [%4];"
        : "=r"(r[0]), "=r"(r[1]), "=r"(r[2]), "=r"(r[3]) : "r"(addr));
}

// quad16 A-layout: 16m x 16k blocks of 256 halves; a thread's m16n8k16 A
// fragment (8 halves) is contiguous (1 LDS.128).
__device__ __forceinline__ size_t q16_off(int m, int k, int K16) {
    return ((size_t)(m >> 4) * K16 + (k >> 4)) * 256
         + (size_t)((((m & 7) << 2) + ((k & 7) >> 1)) * 8
                    + ((k >> 3) & 1) * 4 + ((m >> 3) & 1) * 2 + (k & 1));
}
__device__ __forceinline__ uint32_t packh2(float a, float b) {
    __half2 h = __floats2half2_rn(a, b);
    return *(uint32_t*)&h;
}

// ------------------------------ LayerNorm (quad16 fp16 out) ------------------
__global__ void ln_kernel(const float* __restrict__ x, const float* __restrict__ g,
                          const float* __restrict__ b, __half* __restrict__ o) {
    int row = blockIdx.x;
    int t = threadIdx.x;
    const float4* xr = (const float4*)(x + (size_t)row * DIMV);
    float4 xv = xr[t];
    float s  = xv.x + xv.y + xv.z + xv.w;
    float ss = xv.x*xv.x + xv.y*xv.y + xv.z*xv.z + xv.w*xv.w;
    #pragma unroll
    for (int off = 16; off; off >>= 1) {
        s  += __shfl_xor_sync(0xffffffffu, s,  off);
        ss += __shfl_xor_sync(0xffffffffu, ss, off);
    }
    __shared__ float sh_s[4], sh_ss[4];
    if ((t & 31) == 0) { sh_s[t >> 5] = s; sh_ss[t >> 5] = ss; }
    __syncthreads();
    s  = sh_s[0] + sh_s[1] + sh_s[2] + sh_s[3];
    ss = sh_ss[0] + sh_ss[1] + sh_ss[2] + sh_ss[3];
    float mu  = s * (1.0f / DIMV);
    float var = ss * (1.0f / DIMV) - mu * mu;
    float inv = rsqrtf(var + 1e-5f);
    float4 gv = ((const float4*)g)[t];
    float4 bv = ((const float4*)b)[t];
    float r0 = (xv.x - mu) * inv * gv.x + bv.x;
    float r1 = (xv.y - mu) * inv * gv.y + bv.y;
    float r2 = (xv.z - mu) * inv * gv.z + bv.z;
    float r3 = (xv.w - mu) * inv * gv.w + bv.w;
    int d0 = t * 4;
    *(uint32_t*)(o + q16_off(row, d0,     DIMV / 16)) = packh2(r0, r1);
    *(uint32_t*)(o + q16_off(row, d0 + 2, DIMV / 16)) = packh2(r2, r3);
}

// --------------------------- fp16 rounding copy (plain) ----------------------
__global__ void round16(const float* __restrict__ s, __half* __restrict__ d, int n) {
    int i = blockIdx.x * blockDim.x + threadIdx.x;
    if (i < n) d[i] = __float2half_rn(s[i]);
}

// --------------------------- fp16 tensor-core GEMM ---------------------------
// D[m][n] = sum_k A[m][k]*B[k][n];  A quad16 (LDS.128 frags), acc fp32.
// B smem: plain rows, pitch 136 halves (conflict-free ldmatrix).
// BL=0: B global [k][n]      -> ldmatrix.x4.trans  (rows = k)
// BL=1: B global [token][k]  -> ldmatrix.x4        (rows = token n)
// CTA 128x128, 8 warps, warp tile 64x32. NST=3: one-barrier pipeline; NST=1 single.
// EPI 0 (Wh): s=silu(acc+a0[n]); n<HIDV -> v16 plain; else gate fp32
// EPI 1 (qkT): A16 quad16 = fp16(relu(acc*scale)^2 * A_SCALE)
// EPI 2 (AV): V = acc * A_INV * gate[(z*4096+m)*HIDV+n]
// EPI 3 (Z):  s=silu(acc+a0[n]); q16 quad16; k16 plain
template<int EPI, int BL, int BK, int NST>
__global__ void __launch_bounds__(256, 2)
tgemm(const __half* __restrict__ Ag, int K16g, size_t sA,
      const __half* __restrict__ Bh, int ldbh, size_t sBh,
      void* __restrict__ C0, void* __restrict__ C1,
      int K,
      const float* __restrict__ a0, const float* __restrict__ a1,
      const float* __restrict__ a2, size_t sAux, float scale)
{
    constexpr int KB16   = BK / 16;
    constexpr int ASTG_H = 128 * BK;                       // halves per A stage
    constexpr int BROWS  = BL ? 128 : BK;
    constexpr int BSTG_H = BROWS * 136;

    extern __shared__ __half smh[];
    __half* Asm = smh;
    __half* Bsm = smh + NST * ASTG_H;
    const uint32_t sbA = smem_u32(Asm);
    const uint32_t sbB = smem_u32(Bsm);
    (void)sbA;

    const int z = blockIdx.z;
    const __half* A = Ag + z * sA;
    const __half* B = Bh + z * sBh;
    const float* ax = a0 + z * sAux;

    const int tid  = threadIdx.x;
    const int warp = tid >> 5;
    const int lane = tid & 31;
    const int grp  = lane >> 2;
    const int tig  = lane & 3;
    const int mw   = (warp >> 2) * 64;
    const int nw   = (warp & 3) * 32;
    const int m0 = blockIdx.y * 128, n0 = blockIdx.x * 128;
    const int mbb = (mw >> 4);

    // per-lane ldmatrix base offset (halves, within a stage)
    const int bOff = BL
        ? ((nw + (lane & 7) + 8 * (lane >> 4)) * 136 + 8 * ((lane >> 3) & 1))
        : ((lane & 15) * 136 + (lane >> 4) * 8 + nw);

    float acc[4][4][4];
    #pragma unroll
    for (int mi = 0; mi < 4; mi++)
        #pragma unroll
        for (int ni = 0; ni < 4; ni++)
            #pragma unroll
            for (int r = 0; r < 4; r++) acc[mi][ni][r] = 0.0f;

    auto load_stage = [&](int st, int k0) {
        // A: quad16 blocks, 16B chunks
        #pragma unroll
        for (int l = 0; l < BK / 16; l++) {
            int qc = tid + l * 256;
            int blk = qc >> 5, c = qc & 31;
            int mbl = blk / KB16, kbl = blk - mbl * KB16;
            const __half* gsrc = A + ((size_t)(m0 / 16 + mbl) * K16g + (k0 / 16 + kbl)) * 256 + c * 8;
            cp16(sbB - (NST * ASTG_H - (uint32_t)(st * ASTG_H + blk * 256 + c * 8)) * 2 - 0 + 0
                 , gsrc);
        }
        // B: BROWS rows x 128 halves, 16 chunks/row
        if (BL == 0) {
            #pragma unroll
            for (int l = 0; l < BK / 16; l++) {
                int id = tid + l * 256;
                int r = id >> 4, c = id & 15;
                cp16(sbB + (uint32_t)(st * BSTG_H + r * 136 + c * 8) * 2,
                     B + (size_t)(k0 + r) * ldbh + n0 + c * 8);
            }
        } else {
            #pragma unroll
            for (int l = 0; l < 8; l++) {
                int id = tid + l * 256;
                int r = id >> 4, c = id & 15;
                cp16(sbB + (uint32_t)(st * BSTG_H + r * 136 + c * 8) * 2,
                     B + (size_t)(n0 + r) * ldbh + k0 + c * 8);
            }
        }
        CP_COMMIT();
    };

    auto compute_stage = [&](int st) {
        const __half* As = Asm + st * ASTG_H;
        const uint32_t sbBs = sbB + (uint32_t)(st * BSTG_H) * 2;
        #pragma unroll
        for (int s = 0; s < KB16; s++) {
            uint32_t afr[4][4], bq0[4], bq1[4];
            #pragma unroll
            for (int mi = 0; mi < 4; mi++) {
                uint4 av = *(const uint4*)(As + (((mbb + mi) * KB16 + s) * 256 + lane * 8));
                afr[mi][0] = av.x; afr[mi][1] = av.y; afr[mi][2] = av.z; afr[mi][3] = av.w;
            }
            if (BL == 0) {
                ldsm_x4_t(bq0, sbBs + (uint32_t)(s * 2176 + bOff) * 2);
                ldsm_x4_t(bq1, sbBs + (uint32_t)(s * 2176 + bOff + 16) * 2);
            } else {
                ldsm_x4(bq0, sbBs + (uint32_t)(s * 16 + bOff) * 2);
                ldsm_x4(bq1, sbBs + (uint32_t)(s * 16 + bOff + 16 * 136) * 2);
            }
            uint32_t bfr[4][2] = {
                { bq0[0], bq0[1] }, { bq0[2], bq0[3] },
                { bq1[0], bq1[1] }, { bq1[2], bq1[3] } };
            #pragma unroll
            for (int mi = 0; mi < 4; mi++)
                #pragma unroll
                for (int ni = 0; ni < 4; ni++)
                    mma_f16(acc[mi][ni], afr[mi], bfr[ni]);
        }
    };

    const int niter = K / BK;
    if (NST == 1) {
        load_stage(0, 0);
        CP_WAIT0();
        __syncthreads();
        compute_stage(0);
    } else {
        load_stage(0, 0);
        if (niter > 1) load_stage(1, BK);
        for (int it = 0; it < niter; it++) {
            if (it + 1 < niter) { CP_WAIT1(); }
            else                { CP_WAIT0(); }
            __syncthreads();
            if (it + 2 < niter) load_stage((it + 2) % NST, (it + 2) * BK);
            compute_stage(it % NST);
        }
    }
    __syncthreads();

    // ------------------------------ epilogue ---------------------------------
    #pragma unroll
    for (int mi = 0; mi < 4; mi++) {
        #pragma unroll
        for (int half = 0; half < 2; half++) {
            int m = m0 + mw + mi * 16 + grp + half * 8;
            #pragma unroll
            for (int ni = 0; ni < 4; ni++) {
                int n = n0 + nw + ni * 8 + tig * 2;
                float v0 = acc[mi][ni][half * 2 + 0];
                float v1 = acc[mi][ni][half * 2 + 1];
                if (EPI == 0) {
                    v0 += a0[n];     v1 += a0[n + 1];
                    v0 = v0 / (1.0f + __expf(-v0));
                    v1 = v1 / (1.0f + __expf(-v1));
                    if (n < HIDV) {
                        __half* vv = (__half*)C0;
                        *(uint32_t*)(vv + (size_t)m * HIDV + n) = packh2(v0, v1);
                    } else {
                        float* gb = (float*)C1;
                        *(float2*)(gb + (size_t)m * HIDV + (n - HIDV)) = make_float2(v0, v1);
                    }
                } else if (EPI == 1) {
                    float t0 = fmaxf(v0 * scale, 0.0f);
                    float t1 = fmaxf(v1 * scale, 0.0f);
                    __half* Az = (__half*)C0 + (size_t)z * LSEQ * LSEQ;
                    *(uint32_t*)(Az + q16_off(m, n, LSEQ / 16)) =
                        packh2(t0 * t0 * A_SCALE, t1 * t1 * A_SCALE);
                } else if (EPI == 2) {
                    float* Vp = (float*)C0 + (size_t)z * LSEQ * HIDV;
                    v0 *= A_INV * ax[(size_t)m * HIDV + n];
                    v1 *= A_INV * ax[(size_t)m * HIDV + n + 1];
                    *(float2*)(Vp + (size_t)m * HIDV + n) = make_float2(v0, v1);
                } else {   // EPI 3
                    v0 += a0[n];     v1 += a0[n + 1];
                    v0 = v0 / (1.0f + __expf(-v0));
                    v1 = v1 / (1.0f + __expf(-v1));
                    __half* qb = (__half*)C0;
                    __half* kb = (__half*)C1;
                    *(uint32_t*)(qb + q16_off(m, n, QKD / 16)) =
                        packh2(v0 * a1[n] + a2[n], v1 * a1[n + 1] + a2[n + 1]);
                    *(uint32_t*)(kb + (size_t)m * QKD + n) =
                        packh2(v0 * a1[QKD + n] + a2[QKD + n],
                               v1 * a1[QKD + n + 1] + a2[QKD + n + 1]);
                }
            }
        }
    }
}

// ------------------------- output projection (1024 -> 8) ---------------------
__global__ void out_kernel(const float* __restrict__ Vg, const float* __restrict__ Wo,
                           const float* __restrict__ bo, float* __restrict__ out) {
    int row  = blockIdx.x * (blockDim.x >> 5) + (threadIdx.x >> 5);
    int lane = threadIdx.x & 31;
    const float* vr = Vg + (size_t)row * HIDV;
    float acc[OUTD];
    #pragma unroll
    for (int o = 0; o < OUTD; o++) acc[o] = 0.0f;
    for (int kk = lane; kk < HIDV; kk += 32) {
        float v = vr[kk];
        const float* w = Wo + (size_t)kk * OUTD;
        #pragma unroll
        for (int o = 0; o < OUTD; o++) acc[o] += v * w[o];
    }
    #pragma unroll
    for (int o = 0; o < OUTD; o++) {
        #pragma unroll
        for (int off = 16; off; off >>= 1)
            acc[o] += __shfl_xor_sync(0xffffffffu, acc[o], off);
    }
    if (lane < OUTD) out[(size_t)row * OUTD + lane] = acc[lane] + bo[lane];
}

// --------------------------------- launch ------------------------------------
extern "C" void kernel_launch(void* const* d_in, const int* in_sizes, int n_in,
                              void* d_out, int out_size) {
    const float* x     = (const float*)d_in[0];
    const float* ln_g  = (const float*)d_in[1];
    const float* ln_b  = (const float*)d_in[2];
    const float* Wh    = (const float*)d_in[3];
    const float* bh    = (const float*)d_in[4];
    const float* Wqk   = (const float*)d_in[5];
    const float* bqk   = (const float*)d_in[6];
    const float* gamma = (const float*)d_in[7];
    const float* beta  = (const float*)d_in[8];
    const float* Wo    = (const float*)d_in[9];
    const float* bo    = (const float*)d_in[10];
    float* out = (float*)d_out;

    __half *normed, *Wh16, *Wqk16, *v16, *q16, *k16, *A16;
    float *gate, *V;
    cudaGetSymbolAddress((void**)&normed, g_normed);
    cudaGetSymbolAddress((void**)&Wh16,   g_Wh16);
    cudaGetSymbolAddress((void**)&Wqk16,  g_Wqk16);
    cudaGetSymbolAddress((void**)&v16,    g_v16);
    cudaGetSymbolAddress((void**)&gate,   g_gate);
    cudaGetSymbolAddress((void**)&q16,    g_q16);
    cudaGetSymbolAddress((void**)&k16,    g_k16);
    cudaGetSymbolAddress((void**)&A16,    g_A16);
    cudaGetSymbolAddress((void**)&V,      g_V);

    // One-time stream/event creation (outside capture: first call is the
    // uncaptured correctness run; later capture sees only launches + events).
    static cudaStream_t s1 = nullptr;
    static cudaEvent_t evFork = nullptr, evWh = nullptr;
    if (!s1) {
        cudaStreamCreateWithFlags(&s1, cudaStreamNonBlocking);
        cudaEventCreateWithFlags(&evFork, cudaEventDisableTiming);
        cudaEventCreateWithFlags(&evWh,   cudaEventDisableTiming);
    }

    // smem: BK64/NST3: (3*8192 + 3*8704)*2 = 101376 B
    //       BK128/NST1: (16384 + 17408)*2  = 67584 B
    const int SM_P = 101376, SM_Q = 67584;
    static bool attr_done = false;
    if (!attr_done) {
        cudaFuncSetAttribute(tgemm<0,0,64,3>,  cudaFuncAttributeMaxDynamicSharedMemorySize, SM_P);
        cudaFuncSetAttribute(tgemm<3,0,64,3>,  cudaFuncAttributeMaxDynamicSharedMemorySize, SM_P);
        cudaFuncSetAttribute(tgemm<1,1,128,1>, cudaFuncAttributeMaxDynamicSharedMemorySize, SM_Q);
        cudaFuncSetAttribute(tgemm<2,0,64,3>,  cudaFuncAttributeMaxDynamicSharedMemorySize, SM_P);
        attr_done = true;
    }

    // 0. weights -> fp16 (plain row-major)
    round16<<<(DIMV * HID2 + 255) / 256, 256>>>(Wh,  Wh16,  DIMV * HID2);
    round16<<<(DIMV * QKD  + 255) / 256, 256>>>(Wqk, Wqk16, DIMV * QKD);

    // 1. LayerNorm -> normed (quad16 fp16)
    ln_kernel<<<ROWS, 128>>>(x, ln_g, ln_b, normed);

    // Fork: Wh GEMM runs on s1, concurrent with Z + qkT on the main stream.
    cudaEventRecord(evFork, 0);
    cudaStreamWaitEvent(s1, evFork, 0);

    // 2. Wh GEMM (stream s1): hidden -> v16 (plain) + gate (fp32)
    tgemm<0,0,64,3><<<dim3(HID2 / 128, ROWS / 128, 1), 256, SM_P, s1>>>(
        normed, DIMV / 16, 0, Wh16, HID2, 0,
        v16, gate, DIMV, bh, nullptr, nullptr, 0, 0.0f);
    cudaEventRecord(evWh, s1);

    // 3. Z GEMM fused silu + affine -> q16 (quad16), k16 (plain)   [main stream]
    tgemm<3,0,64,3><<<dim3(1, ROWS / 128, 1), 256, SM_P>>>(
        normed, DIMV / 16, 0, Wqk16, QKD, 0,
        q16, k16, DIMV, bqk, gamma, beta, 0, 0.0f);

    // 4. qkT per batch (K=128, single stage): A16 = fp16(relu(./L)^2 * 2^40)
    tgemm<1,1,128,1><<<dim3(LSEQ / 128, LSEQ / 128, NB), 256, SM_Q>>>(
        q16, QKD / 16, (size_t)LSEQ * QKD, k16, QKD, (size_t)LSEQ * QKD,
        A16, nullptr, QKD, nullptr, nullptr, nullptr, 0, 1.0f / LSEQ);

    // Join: AV needs v16/gate from Wh.
    cudaStreamWaitEvent(0, evWh, 0);

    // 5. AV per batch: V = (A@v) * 2^-40 * gate  (fp32 accumulation)
    tgemm<2,0,64,3><<<dim3(HIDV / 128, LSEQ / 128, NB), 256, SM_P>>>(
        A16, LSEQ / 16, (size_t)LSEQ * LSEQ, v16, HIDV, (size_t)LSEQ * HIDV,
        V, nullptr, LSEQ, gate, nullptr, nullptr, (size_t)LSEQ * HIDV, 0.0f);

    // 6. out = V @ Wo + bo
    out_kernel<<<ROWS / 8, 256>>>(V, Wo, bo, out);
}